// round 11
// baseline (speedup 1.0000x reference)
#include <cuda_runtime.h>

#define K          84
#define CHUNKS     21          // K/4 (16B chunks per row)
#define NPROTO     10
#define HALFP      5           // protos per warp-half
#define THREADS    256
#define SLOT_ROWS  128
#define SLOT_FLOATS (SLOT_ROWS * K)          // 10752
#define SLOT_BYTES  (SLOT_FLOATS * 4)        // 43008
#define NSLOTS     5

// dynamic smem (1 CTA/SM):
//   slots[5][SLOT_FLOATS]  5*43008 = 215040 B
//   wblk[210] ulonglong2   3360 B
//   w2[16] floats          64 B
//   mbar[5] u64            40 B (+pad)
#define SMEM_BYTES (NSLOTS * SLOT_BYTES + CHUNKS * NPROTO * 16 + 64 + 64)

__device__ __forceinline__ void ffma2(unsigned long long &d,
                                      unsigned long long a,
                                      unsigned long long b) {
    asm("fma.rn.f32x2 %0, %1, %2, %0;" : "+l"(d) : "l"(a), "l"(b));
}
__device__ __forceinline__ float f2lo(unsigned long long v) {
    return __int_as_float((unsigned)(v & 0xffffffffULL));
}
__device__ __forceinline__ float f2hi(unsigned long long v) {
    return __int_as_float((unsigned)(v >> 32));
}

__device__ __forceinline__ void mbar_init(unsigned mbar, unsigned count) {
    asm volatile("mbarrier.init.shared.b64 [%0], %1;" :: "r"(mbar), "r"(count) : "memory");
}
__device__ __forceinline__ void mbar_expect_tx(unsigned mbar, unsigned bytes) {
    asm volatile("mbarrier.arrive.expect_tx.shared.b64 _, [%0], %1;"
                 :: "r"(mbar), "r"(bytes) : "memory");
}
__device__ __forceinline__ void mbar_wait(unsigned mbar, unsigned parity) {
    unsigned done;
    asm volatile(
        "{\n\t"
        ".reg .pred p;\n\t"
        "mbarrier.try_wait.parity.acquire.cta.shared::cta.b64 p, [%1], %2;\n\t"
        "selp.b32 %0, 1, 0, p;\n\t"
        "}" : "=r"(done) : "r"(mbar), "r"(parity) : "memory");
    if (!done) {
        asm volatile(
            "{\n\t"
            ".reg .pred P1;\n\t"
            "WAIT_LOOP_%=:\n\t"
            "mbarrier.try_wait.parity.acquire.cta.shared::cta.b64 P1, [%0], %1, 0x989680;\n\t"
            "@P1 bra.uni WAIT_DONE_%=;\n\t"
            "bra.uni WAIT_LOOP_%=;\n\t"
            "WAIT_DONE_%=:\n\t"
            "}" :: "r"(mbar), "r"(parity) : "memory");
    }
}
__device__ __forceinline__ void bulk_g2s(unsigned dst_smem, const void* src,
                                         unsigned bytes, unsigned mbar) {
    asm volatile(
        "cp.async.bulk.shared::cta.global.mbarrier::complete_tx::bytes "
        "[%0], [%1], %2, [%3];"
        :: "r"(dst_smem), "l"(src), "r"(bytes), "r"(mbar) : "memory");
}

__global__ void __launch_bounds__(THREADS, 1)
rbf_kernel(const float* __restrict__ x,
           const float* __restrict__ weight,
           float* __restrict__ out,
           int nrows) {
    extern __shared__ __align__(16) float smem[];
    float* s_slot0 = smem;                                      // [5][SLOT_FLOATS]
    ulonglong2* s_w = (ulonglong2*)(smem + NSLOTS * SLOT_FLOATS); // [210]
    float* s_w2 = (float*)(s_w + CHUNKS * NPROTO);              // [16]
    unsigned long long* s_mbar = (unsigned long long*)(s_w2 + 16); // [5]

    const int t    = threadIdx.x;
    const int tr   = t & (SLOT_ROWS - 1);   // row within slot (0..127)
    const int half = t >> 7;                // 0: protos 0-4, 1: protos 5-9
    const int k0   = half * HALFP;

    // ---- weight blocks: s_w[c*10+k] = chunk c of proto k ----
    for (int i = t; i < CHUNKS * NPROTO; i += THREADS) {
        int c = i / NPROTO;
        int k = i - c * NPROTO;
        const float4 v = *(const float4*)(weight + k * K + 4 * c);
        ulonglong2 u;
        u.x = ((unsigned long long)__float_as_uint(v.y) << 32) | __float_as_uint(v.x);
        u.y = ((unsigned long long)__float_as_uint(v.w) << 32) | __float_as_uint(v.z);
        s_w[i] = u;
    }
    if (t < NPROTO) {
        float s = 0.f;
        #pragma unroll
        for (int j = 0; j < K; j++) { float w = weight[t * K + j]; s += w * w; }
        s_w2[t] = s;
    }

    unsigned mbars[NSLOTS];
    unsigned slot_addr[NSLOTS];
    #pragma unroll
    for (int i = 0; i < NSLOTS; i++) {
        mbars[i] = (unsigned)__cvta_generic_to_shared(&s_mbar[i]);
        slot_addr[i] = (unsigned)__cvta_generic_to_shared(s_slot0 + i * SLOT_FLOATS);
    }
    if (t == 0) {
        #pragma unroll
        for (int i = 0; i < NSLOTS; i++) mbar_init(mbars[i], 1);
    }

    const int nstages = (nrows + SLOT_ROWS - 1) / SLOT_ROWS;  // 4096
    const int step = gridDim.x;
    int count = 0;
    for (long long s = blockIdx.x; s < nstages; s += step) count++;

    __syncthreads();   // weights + mbarrier init visible

    auto issue_stage = [&](int j) {
        if (t == 0) {
            int slot = j % NSLOTS;
            long long stage = (long long)blockIdx.x + (long long)j * step;
            long long row0 = stage * SLOT_ROWS;
            long long rem_rows = (long long)nrows - row0;
            unsigned bytes = (rem_rows >= SLOT_ROWS)
                           ? SLOT_BYTES
                           : (unsigned)(rem_rows * K * 4);
            mbar_expect_tx(mbars[slot], bytes);
            bulk_g2s(slot_addr[slot], x + row0 * K, bytes, mbars[slot]);
        }
    };

    // ---- prologue: fill up to 4 slots ahead + current ----
    #pragma unroll
    for (int p = 0; p < NSLOTS - 1; p++)
        if (p < count) issue_stage(p);

    int slot = 0, parity = 0;
    for (int j = 0; j < count; j++) {
        mbar_wait(mbars[slot], (unsigned)parity);

        const long long stage = (long long)blockIdx.x + (long long)j * step;
        const float* sx = s_slot0 + slot * SLOT_FLOATS;

        const ulonglong2* rowA = (const ulonglong2*)(sx + tr * K);

        unsigned long long acc[HALFP];
        unsigned long long x2a = 0ULL;
        #pragma unroll
        for (int k = 0; k < HALFP; k++) acc[k] = 0ULL;

        #pragma unroll
        for (int c = 0; c < CHUNKS; c++) {
            ulonglong2 va = rowA[c];
            ffma2(x2a, va.x, va.x);
            ffma2(x2a, va.y, va.y);
            #pragma unroll
            for (int k = 0; k < HALFP; k++) {
                ulonglong2 wv = s_w[c * NPROTO + k0 + k];
                ffma2(acc[k], va.x, wv.x);
                ffma2(acc[k], va.y, wv.y);
            }
        }

        float x2A = f2lo(x2a) + f2hi(x2a);

        float res[HALFP];
        #pragma unroll
        for (int k = 0; k < HALFP; k++)
            res[k] = fmaf(-2.f, f2lo(acc[k]) + f2hi(acc[k]), x2A + s_w2[k0 + k]);

        const long long rA = stage * SLOT_ROWS + tr;
        if (rA < nrows) {
            float* o = out + rA * NPROTO;
            if (half == 0) {
                *(float2*)(o + 0) = make_float2(res[0], res[1]);
                *(float2*)(o + 2) = make_float2(res[2], res[3]);
                o[4] = res[4];
            } else {
                o[5] = res[0];
                *(float2*)(o + 6) = make_float2(res[1], res[2]);
                *(float2*)(o + 8) = make_float2(res[3], res[4]);
            }
        }

        __syncthreads();                       // slot fully consumed
        if (j + NSLOTS - 1 < count) issue_stage(j + NSLOTS - 1);

        if (++slot == NSLOTS) { slot = 0; parity ^= 1; }
    }
}

extern "C" void kernel_launch(void* const* d_in, const int* in_sizes, int n_in,
                              void* d_out, int out_size) {
    const float* x = (const float*)d_in[0];
    const float* w = (const float*)d_in[1];
    float* out = (float*)d_out;

    const int nrows = in_sizes[0] / K;   // 524288

    static int nsm = 0;
    if (nsm == 0) {
        cudaFuncSetAttribute(rbf_kernel,
                             cudaFuncAttributeMaxDynamicSharedMemorySize,
                             SMEM_BYTES);
        cudaDeviceGetAttribute(&nsm, cudaDevAttrMultiProcessorCount, 0);
        if (nsm <= 0) nsm = 148;
    }

    // 1 CTA/SM, 8 warps, 5-slot TMA ring: 4 fills (172 KB) in flight per SM
    rbf_kernel<<<nsm, THREADS, SMEM_BYTES>>>(x, w, out, nrows);
}

// round 12
// speedup vs baseline: 1.3176x; 1.3176x over previous
#include <cuda_runtime.h>

#define K          84
#define CHUNKS     21
#define NPROTO     10
#define THREADS    256
#define STAGE_ROWS 256
#define STAGE_FLOATS (STAGE_ROWS * K)        // 21504
#define STAGE_BYTES  (STAGE_FLOATS * 4)      // 86016
#define KSTEPS     11                        // ceil(84/8)

// smem: buf[2][STAGE_FLOATS] + w2[16] + mbar[2]
#define SMEM_BYTES (2 * STAGE_BYTES + 64 + 32)

__device__ __forceinline__ void ffma2(unsigned long long &d,
                                      unsigned long long a,
                                      unsigned long long b) {
    asm("fma.rn.f32x2 %0, %1, %2, %0;" : "+l"(d) : "l"(a), "l"(b));
}
__device__ __forceinline__ float f2lo(unsigned long long v) {
    return __int_as_float((unsigned)(v & 0xffffffffULL));
}
__device__ __forceinline__ float f2hi(unsigned long long v) {
    return __int_as_float((unsigned)(v >> 32));
}

__device__ __forceinline__ void mma_tf32(float &d0, float &d1, float &d2, float &d3,
                                         unsigned a0, unsigned a1, unsigned a2, unsigned a3,
                                         unsigned b0, unsigned b1) {
    asm("mma.sync.aligned.m16n8k8.row.col.f32.tf32.tf32.f32 "
        "{%0,%1,%2,%3},{%4,%5,%6,%7},{%8,%9},{%0,%1,%2,%3};"
        : "+f"(d0), "+f"(d1), "+f"(d2), "+f"(d3)
        : "r"(a0), "r"(a1), "r"(a2), "r"(a3), "r"(b0), "r"(b1));
}

__device__ __forceinline__ void mbar_init(unsigned mbar, unsigned count) {
    asm volatile("mbarrier.init.shared.b64 [%0], %1;" :: "r"(mbar), "r"(count) : "memory");
}
__device__ __forceinline__ void mbar_expect_tx(unsigned mbar, unsigned bytes) {
    asm volatile("mbarrier.arrive.expect_tx.shared.b64 _, [%0], %1;"
                 :: "r"(mbar), "r"(bytes) : "memory");
}
__device__ __forceinline__ void mbar_wait(unsigned mbar, unsigned parity) {
    unsigned done;
    asm volatile(
        "{\n\t"
        ".reg .pred p;\n\t"
        "mbarrier.try_wait.parity.acquire.cta.shared::cta.b64 p, [%1], %2;\n\t"
        "selp.b32 %0, 1, 0, p;\n\t"
        "}" : "=r"(done) : "r"(mbar), "r"(parity) : "memory");
    if (!done) {
        asm volatile(
            "{\n\t"
            ".reg .pred P1;\n\t"
            "WAIT_LOOP_%=:\n\t"
            "mbarrier.try_wait.parity.acquire.cta.shared::cta.b64 P1, [%0], %1, 0x989680;\n\t"
            "@P1 bra.uni WAIT_DONE_%=;\n\t"
            "bra.uni WAIT_LOOP_%=;\n\t"
            "WAIT_DONE_%=:\n\t"
            "}" :: "r"(mbar), "r"(parity) : "memory");
    }
}
__device__ __forceinline__ void bulk_g2s(unsigned dst_smem, const void* src,
                                         unsigned bytes, unsigned mbar) {
    asm volatile(
        "cp.async.bulk.shared::cta.global.mbarrier::complete_tx::bytes "
        "[%0], [%1], %2, [%3];"
        :: "r"(dst_smem), "l"(src), "r"(bytes), "r"(mbar) : "memory");
}

__global__ void __launch_bounds__(THREADS, 1)
rbf_kernel(const float* __restrict__ x,
           const float* __restrict__ weight,
           float* __restrict__ out,
           int nrows) {
    extern __shared__ __align__(16) float smem[];
    float* s_buf0 = smem;                                   // [STAGE_FLOATS]
    float* s_buf1 = smem + STAGE_FLOATS;                    // [STAGE_FLOATS]
    float* s_w2   = smem + 2 * STAGE_FLOATS;                // [16]
    unsigned long long* s_mbar = (unsigned long long*)(s_w2 + 16); // [2]

    const int t    = threadIdx.x;
    const int lane = t & 31;
    const int warp = t >> 5;
    const int lg   = lane >> 2;     // group id 0..7 (fragment row)
    const int lc   = lane & 3;      // id in group (fragment col)

    // ---- B fragments in registers: Bf[nt][s][i], row.col layout ----
    // b0 = w[proto][k], b1 = w[proto][k+4]; proto = nt*8 + lg, k = s*8 + lc
    unsigned Bf[2][KSTEPS][2];
    #pragma unroll
    for (int nt = 0; nt < 2; nt++) {
        int proto = nt * 8 + lg;
        bool pv = proto < NPROTO;
        #pragma unroll
        for (int s = 0; s < KSTEPS; s++) {
            int k0 = s * 8 + lc;
            Bf[nt][s][0] = (pv && k0 < K)     ? __float_as_uint(weight[proto * K + k0])     : 0u;
            Bf[nt][s][1] = (pv && k0 + 4 < K) ? __float_as_uint(weight[proto * K + k0 + 4]) : 0u;
        }
    }

    if (t < NPROTO) {
        float s = 0.f;
        #pragma unroll
        for (int j = 0; j < K; j++) { float w = weight[t * K + j]; s += w * w; }
        s_w2[t] = s;
    }
    if (t >= NPROTO && t < 16) s_w2[t] = 0.f;

    const unsigned mbar0 = (unsigned)__cvta_generic_to_shared(&s_mbar[0]);
    const unsigned mbar1 = (unsigned)__cvta_generic_to_shared(&s_mbar[1]);
    if (t == 0) { mbar_init(mbar0, 1); mbar_init(mbar1, 1); }

    unsigned buf_addr[2];
    buf_addr[0] = (unsigned)__cvta_generic_to_shared(s_buf0);
    buf_addr[1] = (unsigned)__cvta_generic_to_shared(s_buf1);
    const float* bufs[2] = { s_buf0, s_buf1 };
    const unsigned mbars[2] = { mbar0, mbar1 };

    __syncthreads();   // s_w2 + mbarriers visible

    // per-thread w2 values for epilogue columns
    const int   c0   = 2 * lc;          // cols c0, c0+1 (protos 0..7)
    const float w2a  = s_w2[c0];
    const float w2b  = s_w2[c0 + 1];
    const float w2p8 = s_w2[8];
    const float w2p9 = s_w2[9];

    const int nstages = (nrows + STAGE_ROWS - 1) / STAGE_ROWS;  // 2048
    const int step = gridDim.x;
    int count = 0;
    for (long long s = blockIdx.x; s < nstages; s += step) count++;

    auto issue_stage = [&](int j) {
        if (t == 0) {
            long long stage = (long long)blockIdx.x + (long long)j * step;
            long long row0 = stage * STAGE_ROWS;
            long long rem_rows = (long long)nrows - row0;
            unsigned bytes = (rem_rows >= STAGE_ROWS)
                           ? STAGE_BYTES
                           : (unsigned)(rem_rows * K * 4);
            mbar_expect_tx(mbars[j & 1], bytes);
            bulk_g2s(buf_addr[j & 1], x + row0 * K, bytes, mbars[j & 1]);
        }
    };

    if (count > 0) issue_stage(0);
    if (count > 1) issue_stage(1);

    for (int j = 0; j < count; j++) {
        mbar_wait(mbars[j & 1], (unsigned)((j >> 1) & 1));

        const long long stage = (long long)blockIdx.x + (long long)j * step;
        const float* sx = bufs[j & 1];

        // ---- x2 for own row (exact fp32) ----
        float x2r;
        {
            const ulonglong2* rp = (const ulonglong2*)(sx + t * K);
            unsigned long long a0 = 0ULL, a1 = 0ULL;
            #pragma unroll
            for (int c = 0; c < CHUNKS; c++) {
                ulonglong2 v = rp[c];
                ffma2(a0, v.x, v.x);
                ffma2(a1, v.y, v.y);
            }
            x2r = (f2lo(a0) + f2hi(a0)) + (f2lo(a1) + f2hi(a1));
        }

        // ---- two 16-row MMA tiles per warp ----
        #pragma unroll
        for (int mt = 0; mt < 2; mt++) {
            const int mrow = warp * 32 + mt * 16;
            const float* ap0 = sx + (mrow + lg) * K + lc;   // row lg
            const float* ap1 = ap0 + 8 * K;                 // row lg+8

            float d0 = 0.f, d1 = 0.f, d2 = 0.f, d3 = 0.f;   // n-tile 0 (protos 0-7)
            float e0 = 0.f, e1 = 0.f, e2 = 0.f, e3 = 0.f;   // n-tile 1 (protos 8-9)

            #pragma unroll
            for (int s = 0; s < KSTEPS; s++) {
                unsigned a0 = __float_as_uint(ap0[s * 8]);
                unsigned a1 = __float_as_uint(ap1[s * 8]);
                unsigned a2 = (s < 10) ? __float_as_uint(ap0[s * 8 + 4]) : 0u;
                unsigned a3 = (s < 10) ? __float_as_uint(ap1[s * 8 + 4]) : 0u;
                mma_tf32(d0, d1, d2, d3, a0, a1, a2, a3, Bf[0][s][0], Bf[0][s][1]);
                mma_tf32(e0, e1, e2, e3, a0, a1, a2, a3, Bf[1][s][0], Bf[1][s][1]);
            }

            // x2 of the fragment rows via shuffle (rows owned by this warp)
            float x2_0 = __shfl_sync(0xffffffffu, x2r, mt * 16 + lg);
            float x2_1 = __shfl_sync(0xffffffffu, x2r, mt * 16 + 8 + lg);

            const long long grow0 = stage * STAGE_ROWS + mrow + lg;
            const long long grow1 = grow0 + 8;

            if (grow0 < nrows) {
                float* o = out + grow0 * NPROTO;
                *(float2*)(o + c0) = make_float2(fmaf(-2.f, d0, x2_0 + w2a),
                                                 fmaf(-2.f, d1, x2_0 + w2b));
                if (lc == 0)
                    *(float2*)(o + 8) = make_float2(fmaf(-2.f, e0, x2_0 + w2p8),
                                                    fmaf(-2.f, e1, x2_0 + w2p9));
            }
            if (grow1 < nrows) {
                float* o = out + grow1 * NPROTO;
                *(float2*)(o + c0) = make_float2(fmaf(-2.f, d2, x2_1 + w2a),
                                                 fmaf(-2.f, d3, x2_1 + w2b));
                if (lc == 0)
                    *(float2*)(o + 8) = make_float2(fmaf(-2.f, e2, x2_1 + w2p8),
                                                    fmaf(-2.f, e3, x2_1 + w2p9));
            }
        }

        __syncthreads();                 // buffer j&1 fully consumed
        if (j + 2 < count) issue_stage(j + 2);
    }
}

extern "C" void kernel_launch(void* const* d_in, const int* in_sizes, int n_in,
                              void* d_out, int out_size) {
    const float* x = (const float*)d_in[0];
    const float* w = (const float*)d_in[1];
    float* out = (float*)d_out;

    const int nrows = in_sizes[0] / K;   // 524288

    static int nsm = 0;
    if (nsm == 0) {
        cudaFuncSetAttribute(rbf_kernel,
                             cudaFuncAttributeMaxDynamicSharedMemorySize,
                             SMEM_BYTES);
        cudaDeviceGetAttribute(&nsm, cudaDevAttrMultiProcessorCount, 0);
        if (nsm <= 0) nsm = 148;
    }

    // 1 CTA/SM, 8 warps; xw on tensor pipe (tf32 MMA), x2 exact fp32
    rbf_kernel<<<nsm, THREADS, SMEM_BYTES>>>(x, w, out, nrows);
}

// round 13
// speedup vs baseline: 1.3769x; 1.0450x over previous
#include <cuda_runtime.h>

#define K          84
#define CHUNKS     21
#define NPROTO     10
#define THREADS    256
#define SLOT_ROWS  128
#define SLOT_FLOATS (SLOT_ROWS * K)          // 10752
#define SLOT_BYTES  (SLOT_FLOATS * 4)        // 43008
#define NSLOTS     4
#define KSTEPS     11                        // ceil(84/8)

// smem: slots[4][SLOT_FLOATS] + w2[16] + mbar[4]
#define SMEM_BYTES (NSLOTS * SLOT_BYTES + 64 + 64)

__device__ __forceinline__ void ffma2(unsigned long long &d,
                                      unsigned long long a,
                                      unsigned long long b) {
    asm("fma.rn.f32x2 %0, %1, %2, %0;" : "+l"(d) : "l"(a), "l"(b));
}
__device__ __forceinline__ float f2lo(unsigned long long v) {
    return __int_as_float((unsigned)(v & 0xffffffffULL));
}
__device__ __forceinline__ float f2hi(unsigned long long v) {
    return __int_as_float((unsigned)(v >> 32));
}

__device__ __forceinline__ void mma_tf32(float &d0, float &d1, float &d2, float &d3,
                                         unsigned a0, unsigned a1, unsigned a2, unsigned a3,
                                         unsigned b0, unsigned b1) {
    asm("mma.sync.aligned.m16n8k8.row.col.f32.tf32.tf32.f32 "
        "{%0,%1,%2,%3},{%4,%5,%6,%7},{%8,%9},{%0,%1,%2,%3};"
        : "+f"(d0), "+f"(d1), "+f"(d2), "+f"(d3)
        : "r"(a0), "r"(a1), "r"(a2), "r"(a3), "r"(b0), "r"(b1));
}

__device__ __forceinline__ void mbar_init(unsigned mbar, unsigned count) {
    asm volatile("mbarrier.init.shared.b64 [%0], %1;" :: "r"(mbar), "r"(count) : "memory");
}
__device__ __forceinline__ void mbar_expect_tx(unsigned mbar, unsigned bytes) {
    asm volatile("mbarrier.arrive.expect_tx.shared.b64 _, [%0], %1;"
                 :: "r"(mbar), "r"(bytes) : "memory");
}
__device__ __forceinline__ void mbar_wait(unsigned mbar, unsigned parity) {
    unsigned done;
    asm volatile(
        "{\n\t"
        ".reg .pred p;\n\t"
        "mbarrier.try_wait.parity.acquire.cta.shared::cta.b64 p, [%1], %2;\n\t"
        "selp.b32 %0, 1, 0, p;\n\t"
        "}" : "=r"(done) : "r"(mbar), "r"(parity) : "memory");
    if (!done) {
        asm volatile(
            "{\n\t"
            ".reg .pred P1;\n\t"
            "WAIT_LOOP_%=:\n\t"
            "mbarrier.try_wait.parity.acquire.cta.shared::cta.b64 P1, [%0], %1, 0x989680;\n\t"
            "@P1 bra.uni WAIT_DONE_%=;\n\t"
            "bra.uni WAIT_LOOP_%=;\n\t"
            "WAIT_DONE_%=:\n\t"
            "}" :: "r"(mbar), "r"(parity) : "memory");
    }
}
__device__ __forceinline__ void bulk_g2s(unsigned dst_smem, const void* src,
                                         unsigned bytes, unsigned mbar) {
    asm volatile(
        "cp.async.bulk.shared::cta.global.mbarrier::complete_tx::bytes "
        "[%0], [%1], %2, [%3];"
        :: "r"(dst_smem), "l"(src), "r"(bytes), "r"(mbar) : "memory");
}

__global__ void __launch_bounds__(THREADS, 1)
rbf_kernel(const float* __restrict__ x,
           const float* __restrict__ weight,
           float* __restrict__ out,
           int nrows) {
    extern __shared__ __align__(16) float smem[];
    float* s_slots = smem;                                    // [4][SLOT_FLOATS]
    float* s_w2    = smem + NSLOTS * SLOT_FLOATS;             // [16]
    unsigned long long* s_mbar = (unsigned long long*)(s_w2 + 16); // [4]

    const int t    = threadIdx.x;
    const int lane = t & 31;
    const int warp = t >> 5;
    const int lg   = lane >> 2;     // 0..7
    const int lc   = lane & 3;      // 0..3

    // ---- B fragments in registers (row.col): proto = nt*8+lg, k = s*8+lc ----
    unsigned Bf[2][KSTEPS][2];
    #pragma unroll
    for (int nt = 0; nt < 2; nt++) {
        int proto = nt * 8 + lg;
        bool pv = proto < NPROTO;
        #pragma unroll
        for (int s = 0; s < KSTEPS; s++) {
            int k0 = s * 8 + lc;
            Bf[nt][s][0] = (pv && k0 < K)     ? __float_as_uint(weight[proto * K + k0])     : 0u;
            Bf[nt][s][1] = (pv && k0 + 4 < K) ? __float_as_uint(weight[proto * K + k0 + 4]) : 0u;
        }
    }

    if (t < NPROTO) {
        float s = 0.f;
        #pragma unroll
        for (int j = 0; j < K; j++) { float w = weight[t * K + j]; s += w * w; }
        s_w2[t] = s;
    }
    if (t >= NPROTO && t < 16) s_w2[t] = 0.f;

    const unsigned mb_base = (unsigned)__cvta_generic_to_shared(&s_mbar[0]);
    const unsigned sl_base = (unsigned)__cvta_generic_to_shared(s_slots);
    if (t == 0) {
        mbar_init(mb_base + 0,  1);
        mbar_init(mb_base + 8,  1);
        mbar_init(mb_base + 16, 1);
        mbar_init(mb_base + 24, 1);
    }

    __syncthreads();   // s_w2 + mbarriers visible

    const int   c0   = 2 * lc;
    const float w2a  = s_w2[c0];
    const float w2b  = s_w2[c0 + 1];
    const float w2p8 = s_w2[8];
    const float w2p9 = s_w2[9];

    const int nstages = (nrows + SLOT_ROWS - 1) / SLOT_ROWS;  // 4096
    const int step = gridDim.x;
    int count = 0;
    for (long long s = blockIdx.x; s < nstages; s += step) count++;

    // issue fill for local stage j into slot (compile-time literal)
    auto issue_stage = [&](int j, int slot) {
        if (t == 0 && j < count) {
            long long stage = (long long)blockIdx.x + (long long)j * step;
            long long row0 = stage * SLOT_ROWS;
            long long rem_rows = (long long)nrows - row0;
            unsigned bytes = (rem_rows >= SLOT_ROWS)
                           ? SLOT_BYTES
                           : (unsigned)(rem_rows * K * 4);
            mbar_expect_tx(mb_base + slot * 8, bytes);
            bulk_g2s(sl_base + slot * SLOT_BYTES, x + row0 * K, bytes,
                     mb_base + slot * 8);
        }
    };

    // stage body; slot is always a compile-time literal at call sites
    auto body = [&](int j, int slot, int par) {
        mbar_wait(mb_base + slot * 8, (unsigned)par);

        const long long stage = (long long)blockIdx.x + (long long)j * step;
        const float* sx = s_slots + slot * SLOT_FLOATS;

        // ---- x2: lane pairs (l, l+16) split row warp*16 + (l&15) ----
        float x2r;
        {
            const int rloc  = lane & 15;
            const int rhalf = lane >> 4;
            const ulonglong2* rp = (const ulonglong2*)(sx + (warp * 16 + rloc) * K);
            unsigned long long a0 = 0ULL, a1 = 0ULL;
            if (rhalf == 0) {
                #pragma unroll
                for (int c = 0; c < 11; c++) {
                    ulonglong2 v = rp[c];
                    ffma2(a0, v.x, v.x);
                    ffma2(a1, v.y, v.y);
                }
            } else {
                #pragma unroll
                for (int c = 11; c < CHUNKS; c++) {
                    ulonglong2 v = rp[c];
                    ffma2(a0, v.x, v.x);
                    ffma2(a1, v.y, v.y);
                }
            }
            float part = (f2lo(a0) + f2hi(a0)) + (f2lo(a1) + f2hi(a1));
            x2r = part + __shfl_xor_sync(0xffffffffu, part, 16);
        }

        // ---- one 16-row MMA tile per warp ----
        const float* ap0 = sx + (warp * 16 + lg) * K + lc;
        const float* ap1 = ap0 + 8 * K;

        float d0 = 0.f, d1 = 0.f, d2 = 0.f, d3 = 0.f;   // protos 0-7
        float e0 = 0.f, e1 = 0.f, e2 = 0.f, e3 = 0.f;   // protos 8-9

        #pragma unroll
        for (int s = 0; s < KSTEPS; s++) {
            unsigned a0 = __float_as_uint(ap0[s * 8]);
            unsigned a1 = __float_as_uint(ap1[s * 8]);
            unsigned a2 = (s < 10) ? __float_as_uint(ap0[s * 8 + 4]) : 0u;
            unsigned a3 = (s < 10) ? __float_as_uint(ap1[s * 8 + 4]) : 0u;
            mma_tf32(d0, d1, d2, d3, a0, a1, a2, a3, Bf[0][s][0], Bf[0][s][1]);
            mma_tf32(e0, e1, e2, e3, a0, a1, a2, a3, Bf[1][s][0], Bf[1][s][1]);
        }

        float x2_0 = __shfl_sync(0xffffffffu, x2r, lg);
        float x2_1 = __shfl_sync(0xffffffffu, x2r, 8 + lg);

        const long long grow0 = stage * SLOT_ROWS + warp * 16 + lg;
        const long long grow1 = grow0 + 8;

        if (grow0 < nrows) {
            float* o = out + grow0 * NPROTO;
            *(float2*)(o + c0) = make_float2(fmaf(-2.f, d0, x2_0 + w2a),
                                             fmaf(-2.f, d1, x2_0 + w2b));
            if (lc == 0)
                *(float2*)(o + 8) = make_float2(fmaf(-2.f, e0, x2_0 + w2p8),
                                                fmaf(-2.f, e1, x2_0 + w2p9));
        }
        if (grow1 < nrows) {
            float* o = out + grow1 * NPROTO;
            *(float2*)(o + c0) = make_float2(fmaf(-2.f, d2, x2_1 + w2a),
                                             fmaf(-2.f, d3, x2_1 + w2b));
            if (lc == 0)
                *(float2*)(o + 8) = make_float2(fmaf(-2.f, e2, x2_1 + w2p8),
                                                fmaf(-2.f, e3, x2_1 + w2p9));
        }

        __syncthreads();               // slot fully consumed by all warps
        issue_stage(j + NSLOTS, slot); // refill this slot with stage j+4
    };

    // ---- prologue: fill all 4 slots ----
    issue_stage(0, 0);
    issue_stage(1, 1);
    issue_stage(2, 2);
    issue_stage(3, 3);

    int j = 0, par = 0;
    while (j + NSLOTS <= count) {
        body(j,     0, par);
        body(j + 1, 1, par);
        body(j + 2, 2, par);
        body(j + 3, 3, par);
        j += NSLOTS;
        par ^= 1;
    }
    if (j     < count) body(j,     0, par);
    if (j + 1 < count) body(j + 1, 1, par);
    if (j + 2 < count) body(j + 2, 2, par);
}

extern "C" void kernel_launch(void* const* d_in, const int* in_sizes, int n_in,
                              void* d_out, int out_size) {
    const float* x = (const float*)d_in[0];
    const float* w = (const float*)d_in[1];
    float* out = (float*)d_out;

    const int nrows = in_sizes[0] / K;   // 524288

    static int nsm = 0;
    if (nsm == 0) {
        cudaFuncSetAttribute(rbf_kernel,
                             cudaFuncAttributeMaxDynamicSharedMemorySize,
                             SMEM_BYTES);
        cudaDeviceGetAttribute(&nsm, cudaDevAttrMultiProcessorCount, 0);
        if (nsm <= 0) nsm = 148;
    }

    // 1 CTA/SM, 8 warps; tf32 MMA compute + 4-slot TMA ring (compile-time slots)
    rbf_kernel<<<nsm, THREADS, SMEM_BYTES>>>(x, w, out, nrows);
}

// round 14
// speedup vs baseline: 1.3887x; 1.0086x over previous
#include <cuda_runtime.h>

#define K          84
#define CHUNKS     21
#define NPROTO     10
#define THREADS    128          // 4 warps per CTA
#define SLOT_ROWS  64
#define SLOT_FLOATS (SLOT_ROWS * K)          // 5376
#define SLOT_BYTES  (SLOT_FLOATS * 4)        // 21504
#define NSLOTS     4
#define KSTEPS     11                        // ceil(84/8)

// smem per CTA: slots[4][SLOT_FLOATS] + w2[16] + mbar[4]  -> ~86.1 KB, 2 CTAs/SM
#define SMEM_BYTES (NSLOTS * SLOT_BYTES + 64 + 64)

__device__ __forceinline__ void ffma2(unsigned long long &d,
                                      unsigned long long a,
                                      unsigned long long b) {
    asm("fma.rn.f32x2 %0, %1, %2, %0;" : "+l"(d) : "l"(a), "l"(b));
}
__device__ __forceinline__ float f2lo(unsigned long long v) {
    return __int_as_float((unsigned)(v & 0xffffffffULL));
}
__device__ __forceinline__ float f2hi(unsigned long long v) {
    return __int_as_float((unsigned)(v >> 32));
}

__device__ __forceinline__ void mma_tf32(float &d0, float &d1, float &d2, float &d3,
                                         unsigned a0, unsigned a1, unsigned a2, unsigned a3,
                                         unsigned b0, unsigned b1) {
    asm("mma.sync.aligned.m16n8k8.row.col.f32.tf32.tf32.f32 "
        "{%0,%1,%2,%3},{%4,%5,%6,%7},{%8,%9},{%0,%1,%2,%3};"
        : "+f"(d0), "+f"(d1), "+f"(d2), "+f"(d3)
        : "r"(a0), "r"(a1), "r"(a2), "r"(a3), "r"(b0), "r"(b1));
}

__device__ __forceinline__ void mbar_init(unsigned mbar, unsigned count) {
    asm volatile("mbarrier.init.shared.b64 [%0], %1;" :: "r"(mbar), "r"(count) : "memory");
}
__device__ __forceinline__ void mbar_expect_tx(unsigned mbar, unsigned bytes) {
    asm volatile("mbarrier.arrive.expect_tx.shared.b64 _, [%0], %1;"
                 :: "r"(mbar), "r"(bytes) : "memory");
}
__device__ __forceinline__ void mbar_wait(unsigned mbar, unsigned parity) {
    unsigned done;
    asm volatile(
        "{\n\t"
        ".reg .pred p;\n\t"
        "mbarrier.try_wait.parity.acquire.cta.shared::cta.b64 p, [%1], %2;\n\t"
        "selp.b32 %0, 1, 0, p;\n\t"
        "}" : "=r"(done) : "r"(mbar), "r"(parity) : "memory");
    if (!done) {
        asm volatile(
            "{\n\t"
            ".reg .pred P1;\n\t"
            "WAIT_LOOP_%=:\n\t"
            "mbarrier.try_wait.parity.acquire.cta.shared::cta.b64 P1, [%0], %1, 0x989680;\n\t"
            "@P1 bra.uni WAIT_DONE_%=;\n\t"
            "bra.uni WAIT_LOOP_%=;\n\t"
            "WAIT_DONE_%=:\n\t"
            "}" :: "r"(mbar), "r"(parity) : "memory");
    }
}
__device__ __forceinline__ void bulk_g2s(unsigned dst_smem, const void* src,
                                         unsigned bytes, unsigned mbar) {
    asm volatile(
        "cp.async.bulk.shared::cta.global.mbarrier::complete_tx::bytes "
        "[%0], [%1], %2, [%3];"
        :: "r"(dst_smem), "l"(src), "r"(bytes), "r"(mbar) : "memory");
}

__global__ void __launch_bounds__(THREADS, 2)
rbf_kernel(const float* __restrict__ x,
           const float* __restrict__ weight,
           float* __restrict__ out,
           int nrows) {
    extern __shared__ __align__(16) float smem[];
    float* s_slots = smem;                                    // [4][SLOT_FLOATS]
    float* s_w2    = smem + NSLOTS * SLOT_FLOATS;             // [16]
    unsigned long long* s_mbar = (unsigned long long*)(s_w2 + 16); // [4]

    const int t    = threadIdx.x;
    const int lane = t & 31;
    const int warp = t >> 5;       // 0..3
    const int lg   = lane >> 2;    // 0..7
    const int lc   = lane & 3;     // 0..3

    // ---- B fragments in registers (row.col): proto = nt*8+lg, k = s*8+lc ----
    unsigned Bf[2][KSTEPS][2];
    #pragma unroll
    for (int nt = 0; nt < 2; nt++) {
        int proto = nt * 8 + lg;
        bool pv = proto < NPROTO;
        #pragma unroll
        for (int s = 0; s < KSTEPS; s++) {
            int k0 = s * 8 + lc;
            Bf[nt][s][0] = (pv && k0 < K)     ? __float_as_uint(weight[proto * K + k0])     : 0u;
            Bf[nt][s][1] = (pv && k0 + 4 < K) ? __float_as_uint(weight[proto * K + k0 + 4]) : 0u;
        }
    }

    if (t < NPROTO) {
        float s = 0.f;
        #pragma unroll
        for (int j = 0; j < K; j++) { float w = weight[t * K + j]; s += w * w; }
        s_w2[t] = s;
    }
    if (t >= NPROTO && t < 16) s_w2[t] = 0.f;

    const unsigned mb_base = (unsigned)__cvta_generic_to_shared(&s_mbar[0]);
    const unsigned sl_base = (unsigned)__cvta_generic_to_shared(s_slots);
    if (t == 0) {
        mbar_init(mb_base + 0,  1);
        mbar_init(mb_base + 8,  1);
        mbar_init(mb_base + 16, 1);
        mbar_init(mb_base + 24, 1);
    }

    __syncthreads();

    const int   c0   = 2 * lc;
    const float w2a  = s_w2[c0];
    const float w2b  = s_w2[c0 + 1];
    const float w2p8 = s_w2[8];
    const float w2p9 = s_w2[9];

    const int nstages = (nrows + SLOT_ROWS - 1) / SLOT_ROWS;  // 8192
    const int step = gridDim.x;                               // 2*nsm
    int count = 0;
    for (long long s = blockIdx.x; s < nstages; s += step) count++;

    auto issue_stage = [&](int j, int slot) {
        if (t == 0 && j < count) {
            long long stage = (long long)blockIdx.x + (long long)j * step;
            long long row0 = stage * SLOT_ROWS;
            long long rem_rows = (long long)nrows - row0;
            unsigned bytes = (rem_rows >= SLOT_ROWS)
                           ? SLOT_BYTES
                           : (unsigned)(rem_rows * K * 4);
            mbar_expect_tx(mb_base + slot * 8, bytes);
            bulk_g2s(sl_base + slot * SLOT_BYTES, x + row0 * K, bytes,
                     mb_base + slot * 8);
        }
    };

    auto body = [&](int j, int slot, int par) {
        mbar_wait(mb_base + slot * 8, (unsigned)par);

        const long long stage = (long long)blockIdx.x + (long long)j * step;
        const float* sx = s_slots + slot * SLOT_FLOATS;

        // ---- x2: lane pairs (l, l+16) split row warp*16 + (l&15) ----
        float x2r;
        {
            const int rloc  = lane & 15;
            const int rhalf = lane >> 4;
            const ulonglong2* rp = (const ulonglong2*)(sx + (warp * 16 + rloc) * K);
            unsigned long long a0 = 0ULL, a1 = 0ULL;
            if (rhalf == 0) {
                #pragma unroll
                for (int c = 0; c < 11; c++) {
                    ulonglong2 v = rp[c];
                    ffma2(a0, v.x, v.x);
                    ffma2(a1, v.y, v.y);
                }
            } else {
                #pragma unroll
                for (int c = 11; c < CHUNKS; c++) {
                    ulonglong2 v = rp[c];
                    ffma2(a0, v.x, v.x);
                    ffma2(a1, v.y, v.y);
                }
            }
            float part = (f2lo(a0) + f2hi(a0)) + (f2lo(a1) + f2hi(a1));
            x2r = part + __shfl_xor_sync(0xffffffffu, part, 16);
        }

        // ---- one 16-row MMA tile per warp, split accumulator chains ----
        const float* ap0 = sx + (warp * 16 + lg) * K + lc;
        const float* ap1 = ap0 + 8 * K;

        float dA0 = 0.f, dA1 = 0.f, dA2 = 0.f, dA3 = 0.f;   // protos 0-7, k 0-47
        float dB0 = 0.f, dB1 = 0.f, dB2 = 0.f, dB3 = 0.f;   // protos 0-7, k 48-87
        float eA0 = 0.f, eA1 = 0.f, eA2 = 0.f, eA3 = 0.f;   // protos 8-9, k 0-47
        float eB0 = 0.f, eB1 = 0.f, eB2 = 0.f, eB3 = 0.f;   // protos 8-9, k 48-87

        #pragma unroll
        for (int s = 0; s < KSTEPS; s++) {
            unsigned a0 = __float_as_uint(ap0[s * 8]);
            unsigned a1 = __float_as_uint(ap1[s * 8]);
            unsigned a2 = (s < 10) ? __float_as_uint(ap0[s * 8 + 4]) : 0u;
            unsigned a3 = (s < 10) ? __float_as_uint(ap1[s * 8 + 4]) : 0u;
            if (s < 6) {
                mma_tf32(dA0, dA1, dA2, dA3, a0, a1, a2, a3, Bf[0][s][0], Bf[0][s][1]);
                mma_tf32(eA0, eA1, eA2, eA3, a0, a1, a2, a3, Bf[1][s][0], Bf[1][s][1]);
            } else {
                mma_tf32(dB0, dB1, dB2, dB3, a0, a1, a2, a3, Bf[0][s][0], Bf[0][s][1]);
                mma_tf32(eB0, eB1, eB2, eB3, a0, a1, a2, a3, Bf[1][s][0], Bf[1][s][1]);
            }
        }

        float d0 = dA0 + dB0, d1 = dA1 + dB1, d2 = dA2 + dB2, d3 = dA3 + dB3;
        float e0 = eA0 + eB0, e1 = eA1 + eB1, e2 = eA2 + eB2, e3 = eA3 + eB3;

        float x2_0 = __shfl_sync(0xffffffffu, x2r, lg);
        float x2_1 = __shfl_sync(0xffffffffu, x2r, 8 + lg);

        const long long grow0 = stage * SLOT_ROWS + warp * 16 + lg;
        const long long grow1 = grow0 + 8;

        if (grow0 < nrows) {
            float* o = out + grow0 * NPROTO;
            *(float2*)(o + c0) = make_float2(fmaf(-2.f, d0, x2_0 + w2a),
                                             fmaf(-2.f, d1, x2_0 + w2b));
            if (lc == 0)
                *(float2*)(o + 8) = make_float2(fmaf(-2.f, e0, x2_0 + w2p8),
                                                fmaf(-2.f, e1, x2_0 + w2p9));
        }
        if (grow1 < nrows) {
            float* o = out + grow1 * NPROTO;
            *(float2*)(o + c0) = make_float2(fmaf(-2.f, d2, x2_1 + w2a),
                                             fmaf(-2.f, d3, x2_1 + w2b));
            if (lc == 0)
                *(float2*)(o + 8) = make_float2(fmaf(-2.f, e2, x2_1 + w2p8),
                                                fmaf(-2.f, e3, x2_1 + w2p9));
        }

        __syncthreads();               // slot fully consumed (4 warps)
        issue_stage(j + NSLOTS, slot); // refill this slot
    };

    // ---- prologue: fill all 4 slots ----
    issue_stage(0, 0);
    issue_stage(1, 1);
    issue_stage(2, 2);
    issue_stage(3, 3);

    int j = 0, par = 0;
    while (j + NSLOTS <= count) {
        body(j,     0, par);
        body(j + 1, 1, par);
        body(j + 2, 2, par);
        body(j + 3, 3, par);
        j += NSLOTS;
        par ^= 1;
    }
    if (j     < count) body(j,     0, par);
    if (j + 1 < count) body(j + 1, 1, par);
    if (j + 2 < count) body(j + 2, 2, par);
}

extern "C" void kernel_launch(void* const* d_in, const int* in_sizes, int n_in,
                              void* d_out, int out_size) {
    const float* x = (const float*)d_in[0];
    const float* w = (const float*)d_in[1];
    float* out = (float*)d_out;

    const int nrows = in_sizes[0] / K;   // 524288

    static int nsm = 0;
    if (nsm == 0) {
        cudaFuncSetAttribute(rbf_kernel,
                             cudaFuncAttributeMaxDynamicSharedMemorySize,
                             SMEM_BYTES);
        cudaDeviceGetAttribute(&nsm, cudaDevAttrMultiProcessorCount, 0);
        if (nsm <= 0) nsm = 148;
    }

    // 2 CTAs/SM x 4 warps; tf32 MMA (split chains) + 4-slot TMA ring of 21.5 KB fills
    rbf_kernel<<<2 * nsm, THREADS, SMEM_BYTES>>>(x, w, out, nrows);
}